// round 11
// baseline (speedup 1.0000x reference)
#include <cuda_runtime.h>
#include <cstdint>

// ---------------------------------------------------------------------------
// Problem constants (fixed by the reference)
// ---------------------------------------------------------------------------
#define B_GRAPHS 64      // graphs in batch
#define D 128            // D_NODE == D_REG
#define H1DIM 256        // hidden
#define H2DIM 128        // hidden/2
#define PNUM 64          // partitions
#define TM 64            // boundary rows per block in main kernel

// ---------------------------------------------------------------------------
// Device scratch (no allocations allowed -> __device__ globals)
// ---------------------------------------------------------------------------
__device__ float g_sums[B_GRAPHS * D];
__device__ float g_cnt[B_GRAPHS];
__device__ float g_contrib_ns[B_GRAPHS * H1DIM];  // gc part of layer1 + b1 folded in
__device__ float g_contrib_ps[B_GRAPHS * H1DIM];
__device__ int   g_mask_kind;                     // 0=byte, 1=int32, 2=float32

// ---------------------------------------------------------------------------
// Kernel 0: zero the segment accumulators (graph replay must be deterministic)
// ---------------------------------------------------------------------------
__global__ void k_zero() {
    int t = blockIdx.x * blockDim.x + threadIdx.x;
    if (t < B_GRAPHS * D) g_sums[t] = 0.f;
    if (t < B_GRAPHS)     g_cnt[t]  = 0.f;
}

// ---------------------------------------------------------------------------
// Kernel 1: segment-sum of region embeddings + counts
// ---------------------------------------------------------------------------
__global__ void k_segsum(const float* __restrict__ re,
                         const int* __restrict__ rb, int R) {
    int idx = blockIdx.x * blockDim.x + threadIdx.x;
    int total = R * D;
    if (idx < total) {
        int r = idx >> 7;          // / D
        int d = idx & (D - 1);
        atomicAdd(&g_sums[rb[r] * D + d], re[idx]);
    }
    if (idx < R) atomicAdd(&g_cnt[rb[idx]], 1.f);
}

// ---------------------------------------------------------------------------
// Kernel 2: detect action_mask storage dtype (bool is not a harness dtype).
// Deterministic: depends only on input bytes.
// ---------------------------------------------------------------------------
__global__ void k_detect(const unsigned int* __restrict__ w, int nwords) {
    __shared__ int not_int, not_float;
    if (threadIdx.x == 0) { not_int = 0; not_float = 0; }
    __syncthreads();
    int li = 0, lf = 0;
    for (int i = threadIdx.x; i < nwords; i += blockDim.x) {
        unsigned v = w[i];
        if (v > 1u) li = 1;                           // not plausible int32 bool
        if (v != 0u && v != 0x3f800000u) lf = 1;      // not plausible f32 bool
    }
    if (li) not_int = 1;
    if (lf) not_float = 1;
    __syncthreads();
    if (threadIdx.x == 0)
        g_mask_kind = not_int ? (not_float ? 0 : 2) : 1;
}

// ---------------------------------------------------------------------------
// Kernel 3: per-batch global context MLP + per-batch layer-1 contribution
//   mean   = sums/max(cnt,1)                              [64,128]
//   gc     = relu(mean@ge_w1+ge_b1)@ge_w2+ge_b2           [64,128]
//   contrib_h[b][j] = sum_k gc[b][k]*h_w1[128+k][j] + h_b1[j]   (both heads)
// One block per batch, 256 threads.
// ---------------------------------------------------------------------------
__global__ void k_global(const float* __restrict__ ge_w1, const float* __restrict__ ge_b1,
                         const float* __restrict__ ge_w2, const float* __restrict__ ge_b2,
                         const float* __restrict__ ns_w1, const float* __restrict__ ns_b1,
                         const float* __restrict__ ps_w1, const float* __restrict__ ps_b1) {
    __shared__ float mean[D], h[H1DIM], gc[D];
    int b = blockIdx.x, t = threadIdx.x;
    if (t < D) mean[t] = g_sums[b * D + t] / fmaxf(g_cnt[b], 1.f);
    __syncthreads();
    {
        float a = ge_b1[t];
        #pragma unroll 4
        for (int k = 0; k < D; ++k) a = fmaf(mean[k], ge_w1[k * H1DIM + t], a);
        h[t] = fmaxf(a, 0.f);
    }
    __syncthreads();
    if (t < D) {
        float a = ge_b2[t];
        #pragma unroll 4
        for (int j = 0; j < H1DIM; ++j) a = fmaf(h[j], ge_w2[j * D + t], a);
        gc[t] = a;
    }
    __syncthreads();
    {
        float cn = ns_b1[t], cp = ps_b1[t];
        #pragma unroll 4
        for (int k = 0; k < D; ++k) {
            float g = gc[k];
            cn = fmaf(g, ns_w1[(D + k) * H1DIM + t], cn);
            cp = fmaf(g, ps_w1[(D + k) * H1DIM + t], cp);
        }
        g_contrib_ns[b * H1DIM + t] = cn;
        g_contrib_ps[b * H1DIM + t] = cp;
    }
}

// ---------------------------------------------------------------------------
// Main fused kernel: per 64 boundary rows, run both 3-layer MLP heads.
// 256 threads, register-blocked FFMA GEMMs, weights staged through smem.
//
// Dynamic smem layout (floats):
//   xs : [64][132]      node-embedding half of the input   (offset 0,    8448)
//   h1 : [64][256]      layer-1 activations / ps_w3 stage  (offset 8448, 16384)
//   h2 : [64][132]      layer-2 activations                (offset 24832, 8448)
//   wt : [4096]         weight tile staging                (offset 33280, 4096)
//   nid/bid : 128 ints                                     (offset 37376)
// total = 37504 floats = 150016 bytes
// ---------------------------------------------------------------------------
#define SM_XS 0
#define SM_H1 8448
#define SM_H2 24832
#define SM_WT 33280
#define SM_ID 37376
#define SMEM_BYTES 150016

__global__ __launch_bounds__(256) void k_main(
    const float* __restrict__ node_emb,
    const int*   __restrict__ boundary,
    const int*   __restrict__ nbidx,
    const void*  __restrict__ amask,
    const float* __restrict__ ns_w1, const float* __restrict__ ns_w2,
    const float* __restrict__ ns_b2, const float* __restrict__ ns_w3,
    const float* __restrict__ ns_b3,
    const float* __restrict__ ps_w1, const float* __restrict__ ps_w2,
    const float* __restrict__ ps_b2, const float* __restrict__ ps_w3,
    const float* __restrict__ ps_b3,
    float* __restrict__ out_node, float* __restrict__ out_part,
    int NB)
{
    extern __shared__ float sm[];
    float* xs = sm + SM_XS;     // row stride 132
    float* h1 = sm + SM_H1;     // row stride 256
    float* h2 = sm + SM_H2;     // row stride 132
    float* wt = sm + SM_WT;
    int*  nid = (int*)(sm + SM_ID);
    int*  bid = nid + TM;

    const int tid = threadIdx.x;
    const int cg  = tid & 31;   // lane -> column group
    const int rg  = tid >> 5;   // warp -> row group
    const int rb0 = rg * 8;
    const int base = blockIdx.x * TM;

    // --- gather row indices + batch indices ---
    if (tid < TM) {
        int row = base + tid;
        int n = boundary[row < NB ? row : (NB - 1)];
        nid[tid] = n;
        bid[tid] = nbidx[n];
    }
    __syncthreads();

    // --- gather node embeddings into xs (warp r loads row r, float4) ---
    for (int r = rg; r < TM; r += 8) {
        const float4* src = (const float4*)(node_emb + (size_t)nid[r] * D);
        ((float4*)(xs + r * 132))[cg] = src[cg];
    }
    __syncthreads();

    for (int head = 0; head < 2; ++head) {
        const float* w1      = head ? ps_w1 : ns_w1;
        const float* contrib = head ? g_contrib_ps : g_contrib_ns;
        const float* w2      = head ? ps_w2 : ns_w2;
        const float* b2      = head ? ps_b2 : ns_b2;

        // ---------------- layer 1: [64,128] x [128,256] ----------------
        float acc[8][8];
        #pragma unroll
        for (int j = 0; j < 8; ++j)
            #pragma unroll
            for (int i = 0; i < 8; ++i) acc[j][i] = 0.f;

        for (int k0 = 0; k0 < D; k0 += 16) {
            __syncthreads();
            #pragma unroll
            for (int it = 0; it < 16; ++it) {
                int idx = tid + it * 256;
                wt[idx] = w1[(k0 + (idx >> 8)) * H1DIM + (idx & 255)];
            }
            __syncthreads();
            #pragma unroll
            for (int kk = 0; kk < 16; ++kk) {
                float xr[8], wf[8];
                #pragma unroll
                for (int j = 0; j < 8; ++j) xr[j] = xs[(rb0 + j) * 132 + k0 + kk];
                #pragma unroll
                for (int i = 0; i < 8; ++i) wf[i] = wt[kk * 256 + cg + 32 * i];
                #pragma unroll
                for (int j = 0; j < 8; ++j)
                    #pragma unroll
                    for (int i = 0; i < 8; ++i)
                        acc[j][i] = fmaf(xr[j], wf[i], acc[j][i]);
            }
        }
        __syncthreads();
        #pragma unroll
        for (int j = 0; j < 8; ++j) {
            int row = rb0 + j;
            const float* cb = contrib + bid[row] * H1DIM;
            #pragma unroll
            for (int i = 0; i < 8; ++i) {
                int c = cg + 32 * i;
                h1[row * 256 + c] = fmaxf(acc[j][i] + cb[c], 0.f);
            }
        }
        __syncthreads();

        // ---------------- layer 2: [64,256] x [256,128] ----------------
        float a2[8][4];
        #pragma unroll
        for (int j = 0; j < 8; ++j)
            #pragma unroll
            for (int i = 0; i < 4; ++i) a2[j][i] = 0.f;

        for (int k0 = 0; k0 < H1DIM; k0 += 16) {
            __syncthreads();
            #pragma unroll
            for (int it = 0; it < 8; ++it) {
                int idx = tid + it * 256;
                wt[idx] = w2[(k0 + (idx >> 7)) * H2DIM + (idx & 127)];
            }
            __syncthreads();
            #pragma unroll
            for (int kk = 0; kk < 16; ++kk) {
                float xr[8], wf[4];
                #pragma unroll
                for (int j = 0; j < 8; ++j) xr[j] = h1[(rb0 + j) * 256 + k0 + kk];
                #pragma unroll
                for (int i = 0; i < 4; ++i) wf[i] = wt[kk * 128 + cg + 32 * i];
                #pragma unroll
                for (int j = 0; j < 8; ++j)
                    #pragma unroll
                    for (int i = 0; i < 4; ++i)
                        a2[j][i] = fmaf(xr[j], wf[i], a2[j][i]);
            }
        }
        __syncthreads();
        #pragma unroll
        for (int j = 0; j < 8; ++j) {
            int row = rb0 + j;
            #pragma unroll
            for (int i = 0; i < 4; ++i) {
                int c = cg + 32 * i;
                h2[row * 132 + c] = fmaxf(a2[j][i] + b2[c], 0.f);
            }
        }
        __syncthreads();

        // ---------------- layer 3 ----------------
        if (head == 0) {
            // node logits: [64,128] x [128,1]
            if (tid < TM) {
                float s = ns_b3[0];
                const float* hr = h2 + tid * 132;
                #pragma unroll 4
                for (int d2 = 0; d2 < H2DIM; ++d2) s = fmaf(hr[d2], ns_w3[d2], s);
                int row = base + tid;
                if (row < NB) out_node[row] = s;
            }
            // next head begins with __syncthreads() before touching h1/h2
        } else {
            // partition logits: [64,128] x [128,64] + mask
            float* w3s = h1;   // h1 is dead now; reuse as ps_w3 stage (8192 floats)
            __syncthreads();
            #pragma unroll
            for (int it = 0; it < 32; ++it)
                w3s[tid + it * 256] = ps_w3[tid + it * 256];
            __syncthreads();

            float a3[8][2];
            #pragma unroll
            for (int j = 0; j < 8; ++j) { a3[j][0] = 0.f; a3[j][1] = 0.f; }
            #pragma unroll 4
            for (int d2 = 0; d2 < H2DIM; ++d2) {
                float w0 = w3s[d2 * PNUM + cg];
                float w1v = w3s[d2 * PNUM + cg + 32];
                #pragma unroll
                for (int j = 0; j < 8; ++j) {
                    float x = h2[(rb0 + j) * 132 + d2];
                    a3[j][0] = fmaf(x, w0, a3[j][0]);
                    a3[j][1] = fmaf(x, w1v, a3[j][1]);
                }
            }
            int kind = g_mask_kind;
            #pragma unroll
            for (int j = 0; j < 8; ++j) {
                int row  = rb0 + j;
                int grow = base + row;
                if (grow >= NB) continue;
                size_t n = (size_t)nid[row];
                #pragma unroll
                for (int i = 0; i < 2; ++i) {
                    int p = cg + 32 * i;
                    float v = a3[j][i] + ps_b3[p];
                    size_t off = n * PNUM + p;
                    bool m;
                    if (kind == 0)      m = ((const unsigned char*)amask)[off] != 0;
                    else if (kind == 1) m = ((const int*)amask)[off] != 0;
                    else                m = ((const float*)amask)[off] != 0.f;
                    out_part[(size_t)grow * PNUM + p] = m ? v : -1e9f;
                }
            }
        }
    }
}

// ---------------------------------------------------------------------------
// Launcher
// ---------------------------------------------------------------------------
extern "C" void kernel_launch(void* const* d_in, const int* in_sizes, int n_in,
                              void* d_out, int out_size) {
    const float* node_emb   = (const float*)d_in[0];
    const float* region_emb = (const float*)d_in[1];
    const int*   boundary   = (const int*)d_in[2];
    const int*   nbidx      = (const int*)d_in[3];
    const int*   rbidx      = (const int*)d_in[4];
    const void*  amask      = d_in[5];
    const float* ge_w1 = (const float*)d_in[6];
    const float* ge_b1 = (const float*)d_in[7];
    const float* ge_w2 = (const float*)d_in[8];
    const float* ge_b2 = (const float*)d_in[9];
    const float* ns_w1 = (const float*)d_in[10];
    const float* ns_b1 = (const float*)d_in[11];
    const float* ns_w2 = (const float*)d_in[12];
    const float* ns_b2 = (const float*)d_in[13];
    const float* ns_w3 = (const float*)d_in[14];
    const float* ns_b3 = (const float*)d_in[15];
    const float* ps_w1 = (const float*)d_in[16];
    const float* ps_b1 = (const float*)d_in[17];
    const float* ps_w2 = (const float*)d_in[18];
    const float* ps_b2 = (const float*)d_in[19];
    const float* ps_w3 = (const float*)d_in[20];
    const float* ps_b3 = (const float*)d_in[21];

    const int NB = in_sizes[2];
    const int R  = in_sizes[4];
    const int maskElems = in_sizes[5];

    float* out_node = (float*)d_out;
    float* out_part = out_node + NB;

    // idempotent; legal during graph capture (not a stream operation)
    cudaFuncSetAttribute(k_main, cudaFuncAttributeMaxDynamicSharedMemorySize,
                         SMEM_BYTES);

    k_zero<<<(B_GRAPHS * D + 255) / 256, 256>>>();
    k_segsum<<<(R * D + 255) / 256, 256>>>(region_emb, rbidx, R);

    int nwords = maskElems / 4;          // safe lower bound on buffer words
    if (nwords > 65536) nwords = 65536;
    k_detect<<<1, 256>>>((const unsigned int*)amask, nwords);

    k_global<<<B_GRAPHS, 256>>>(ge_w1, ge_b1, ge_w2, ge_b2,
                                ns_w1, ns_b1, ps_w1, ps_b1);

    int grid = (NB + TM - 1) / TM;
    k_main<<<grid, 256, SMEM_BYTES>>>(node_emb, boundary, nbidx, amask,
                                      ns_w1, ns_w2, ns_b2, ns_w3, ns_b3,
                                      ps_w1, ps_w2, ps_b2, ps_w3, ps_b3,
                                      out_node, out_part, NB);
}

// round 12
// speedup vs baseline: 1.0011x; 1.0011x over previous
#include <cuda_runtime.h>
#include <cstdint>

// ---------------------------------------------------------------------------
// Problem constants (fixed by the reference)
// ---------------------------------------------------------------------------
#define B_GRAPHS 64      // graphs in batch
#define D 128            // D_NODE == D_REG
#define H1DIM 256        // hidden
#define H2DIM 128        // hidden/2
#define PNUM 64          // partitions
#define TM 64            // boundary rows per block in main kernel

// ---------------------------------------------------------------------------
// Device scratch (no allocations allowed -> __device__ globals)
// ---------------------------------------------------------------------------
__device__ float g_sums[B_GRAPHS * D];
__device__ float g_cnt[B_GRAPHS];
__device__ float g_contrib_ns[B_GRAPHS * H1DIM];  // gc part of layer1 + b1 folded in
__device__ float g_contrib_ps[B_GRAPHS * H1DIM];
__device__ int   g_mask_kind;                     // 0=byte, 1=int32, 2=float32

// ---------------------------------------------------------------------------
// Kernel 0: zero the segment accumulators (graph replay must be deterministic)
// ---------------------------------------------------------------------------
__global__ void k_zero() {
    int t = blockIdx.x * blockDim.x + threadIdx.x;
    if (t < B_GRAPHS * D) g_sums[t] = 0.f;
    if (t < B_GRAPHS)     g_cnt[t]  = 0.f;
}

// ---------------------------------------------------------------------------
// Kernel 1: segment-sum of region embeddings + counts
// ---------------------------------------------------------------------------
__global__ void k_segsum(const float* __restrict__ re,
                         const int* __restrict__ rb, int R) {
    int idx = blockIdx.x * blockDim.x + threadIdx.x;
    int total = R * D;
    if (idx < total) {
        int r = idx >> 7;          // / D
        int d = idx & (D - 1);
        atomicAdd(&g_sums[rb[r] * D + d], re[idx]);
    }
    if (idx < R) atomicAdd(&g_cnt[rb[idx]], 1.f);
}

// ---------------------------------------------------------------------------
// Kernel 2: detect action_mask storage dtype (bool is not a harness dtype).
// Deterministic: depends only on input bytes.
// ---------------------------------------------------------------------------
__global__ void k_detect(const unsigned int* __restrict__ w, int nwords) {
    __shared__ int not_int, not_float;
    if (threadIdx.x == 0) { not_int = 0; not_float = 0; }
    __syncthreads();
    int li = 0, lf = 0;
    for (int i = threadIdx.x; i < nwords; i += blockDim.x) {
        unsigned v = w[i];
        if (v > 1u) li = 1;                           // not plausible int32 bool
        if (v != 0u && v != 0x3f800000u) lf = 1;      // not plausible f32 bool
    }
    if (li) not_int = 1;
    if (lf) not_float = 1;
    __syncthreads();
    if (threadIdx.x == 0)
        g_mask_kind = not_int ? (not_float ? 0 : 2) : 1;
}

// ---------------------------------------------------------------------------
// Kernel 3: per-batch global context MLP + per-batch layer-1 contribution
//   mean   = sums/max(cnt,1)                              [64,128]
//   gc     = relu(mean@ge_w1+ge_b1)@ge_w2+ge_b2           [64,128]
//   contrib_h[b][j] = sum_k gc[b][k]*h_w1[128+k][j] + h_b1[j]   (both heads)
// One block per batch, 256 threads.
// ---------------------------------------------------------------------------
__global__ void k_global(const float* __restrict__ ge_w1, const float* __restrict__ ge_b1,
                         const float* __restrict__ ge_w2, const float* __restrict__ ge_b2,
                         const float* __restrict__ ns_w1, const float* __restrict__ ns_b1,
                         const float* __restrict__ ps_w1, const float* __restrict__ ps_b1) {
    __shared__ float mean[D], h[H1DIM], gc[D];
    int b = blockIdx.x, t = threadIdx.x;
    if (t < D) mean[t] = g_sums[b * D + t] / fmaxf(g_cnt[b], 1.f);
    __syncthreads();
    {
        float a = ge_b1[t];
        #pragma unroll 4
        for (int k = 0; k < D; ++k) a = fmaf(mean[k], ge_w1[k * H1DIM + t], a);
        h[t] = fmaxf(a, 0.f);
    }
    __syncthreads();
    if (t < D) {
        float a = ge_b2[t];
        #pragma unroll 4
        for (int j = 0; j < H1DIM; ++j) a = fmaf(h[j], ge_w2[j * D + t], a);
        gc[t] = a;
    }
    __syncthreads();
    {
        float cn = ns_b1[t], cp = ps_b1[t];
        #pragma unroll 4
        for (int k = 0; k < D; ++k) {
            float g = gc[k];
            cn = fmaf(g, ns_w1[(D + k) * H1DIM + t], cn);
            cp = fmaf(g, ps_w1[(D + k) * H1DIM + t], cp);
        }
        g_contrib_ns[b * H1DIM + t] = cn;
        g_contrib_ps[b * H1DIM + t] = cp;
    }
}

// ---------------------------------------------------------------------------
// Main fused kernel: per 64 boundary rows, run both 3-layer MLP heads.
// 256 threads, register-blocked FFMA GEMMs, weights staged through smem.
//
// Dynamic smem layout (floats):
//   xs : [64][132]      node-embedding half of the input   (offset 0,    8448)
//   h1 : [64][256]      layer-1 activations / ps_w3 stage  (offset 8448, 16384)
//   h2 : [64][132]      layer-2 activations                (offset 24832, 8448)
//   wt : [4096]         weight tile staging                (offset 33280, 4096)
//   nid/bid : 128 ints                                     (offset 37376)
// total = 37504 floats = 150016 bytes
// ---------------------------------------------------------------------------
#define SM_XS 0
#define SM_H1 8448
#define SM_H2 24832
#define SM_WT 33280
#define SM_ID 37376
#define SMEM_BYTES 150016

__global__ __launch_bounds__(256) void k_main(
    const float* __restrict__ node_emb,
    const int*   __restrict__ boundary,
    const int*   __restrict__ nbidx,
    const void*  __restrict__ amask,
    const float* __restrict__ ns_w1, const float* __restrict__ ns_w2,
    const float* __restrict__ ns_b2, const float* __restrict__ ns_w3,
    const float* __restrict__ ns_b3,
    const float* __restrict__ ps_w1, const float* __restrict__ ps_w2,
    const float* __restrict__ ps_b2, const float* __restrict__ ps_w3,
    const float* __restrict__ ps_b3,
    float* __restrict__ out_node, float* __restrict__ out_part,
    int NB)
{
    extern __shared__ float sm[];
    float* xs = sm + SM_XS;     // row stride 132
    float* h1 = sm + SM_H1;     // row stride 256
    float* h2 = sm + SM_H2;     // row stride 132
    float* wt = sm + SM_WT;
    int*  nid = (int*)(sm + SM_ID);
    int*  bid = nid + TM;

    const int tid = threadIdx.x;
    const int cg  = tid & 31;   // lane -> column group
    const int rg  = tid >> 5;   // warp -> row group
    const int rb0 = rg * 8;
    const int base = blockIdx.x * TM;

    // --- gather row indices + batch indices ---
    if (tid < TM) {
        int row = base + tid;
        int n = boundary[row < NB ? row : (NB - 1)];
        nid[tid] = n;
        bid[tid] = nbidx[n];
    }
    __syncthreads();

    // --- gather node embeddings into xs (warp r loads row r, float4) ---
    for (int r = rg; r < TM; r += 8) {
        const float4* src = (const float4*)(node_emb + (size_t)nid[r] * D);
        ((float4*)(xs + r * 132))[cg] = src[cg];
    }
    __syncthreads();

    for (int head = 0; head < 2; ++head) {
        const float* w1      = head ? ps_w1 : ns_w1;
        const float* contrib = head ? g_contrib_ps : g_contrib_ns;
        const float* w2      = head ? ps_w2 : ns_w2;
        const float* b2      = head ? ps_b2 : ns_b2;

        // ---------------- layer 1: [64,128] x [128,256] ----------------
        float acc[8][8];
        #pragma unroll
        for (int j = 0; j < 8; ++j)
            #pragma unroll
            for (int i = 0; i < 8; ++i) acc[j][i] = 0.f;

        for (int k0 = 0; k0 < D; k0 += 16) {
            __syncthreads();
            #pragma unroll
            for (int it = 0; it < 16; ++it) {
                int idx = tid + it * 256;
                wt[idx] = w1[(k0 + (idx >> 8)) * H1DIM + (idx & 255)];
            }
            __syncthreads();
            #pragma unroll
            for (int kk = 0; kk < 16; ++kk) {
                float xr[8], wf[8];
                #pragma unroll
                for (int j = 0; j < 8; ++j) xr[j] = xs[(rb0 + j) * 132 + k0 + kk];
                #pragma unroll
                for (int i = 0; i < 8; ++i) wf[i] = wt[kk * 256 + cg + 32 * i];
                #pragma unroll
                for (int j = 0; j < 8; ++j)
                    #pragma unroll
                    for (int i = 0; i < 8; ++i)
                        acc[j][i] = fmaf(xr[j], wf[i], acc[j][i]);
            }
        }
        __syncthreads();
        #pragma unroll
        for (int j = 0; j < 8; ++j) {
            int row = rb0 + j;
            const float* cb = contrib + bid[row] * H1DIM;
            #pragma unroll
            for (int i = 0; i < 8; ++i) {
                int c = cg + 32 * i;
                h1[row * 256 + c] = fmaxf(acc[j][i] + cb[c], 0.f);
            }
        }
        __syncthreads();

        // ---------------- layer 2: [64,256] x [256,128] ----------------
        float a2[8][4];
        #pragma unroll
        for (int j = 0; j < 8; ++j)
            #pragma unroll
            for (int i = 0; i < 4; ++i) a2[j][i] = 0.f;

        for (int k0 = 0; k0 < H1DIM; k0 += 16) {
            __syncthreads();
            #pragma unroll
            for (int it = 0; it < 8; ++it) {
                int idx = tid + it * 256;
                wt[idx] = w2[(k0 + (idx >> 7)) * H2DIM + (idx & 127)];
            }
            __syncthreads();
            #pragma unroll
            for (int kk = 0; kk < 16; ++kk) {
                float xr[8], wf[4];
                #pragma unroll
                for (int j = 0; j < 8; ++j) xr[j] = h1[(rb0 + j) * 256 + k0 + kk];
                #pragma unroll
                for (int i = 0; i < 4; ++i) wf[i] = wt[kk * 128 + cg + 32 * i];
                #pragma unroll
                for (int j = 0; j < 8; ++j)
                    #pragma unroll
                    for (int i = 0; i < 4; ++i)
                        a2[j][i] = fmaf(xr[j], wf[i], a2[j][i]);
            }
        }
        __syncthreads();
        #pragma unroll
        for (int j = 0; j < 8; ++j) {
            int row = rb0 + j;
            #pragma unroll
            for (int i = 0; i < 4; ++i) {
                int c = cg + 32 * i;
                h2[row * 132 + c] = fmaxf(a2[j][i] + b2[c], 0.f);
            }
        }
        __syncthreads();

        // ---------------- layer 3 ----------------
        if (head == 0) {
            // node logits: [64,128] x [128,1]
            if (tid < TM) {
                float s = ns_b3[0];
                const float* hr = h2 + tid * 132;
                #pragma unroll 4
                for (int d2 = 0; d2 < H2DIM; ++d2) s = fmaf(hr[d2], ns_w3[d2], s);
                int row = base + tid;
                if (row < NB) out_node[row] = s;
            }
            // next head begins with __syncthreads() before touching h1/h2
        } else {
            // partition logits: [64,128] x [128,64] + mask
            float* w3s = h1;   // h1 is dead now; reuse as ps_w3 stage (8192 floats)
            __syncthreads();
            #pragma unroll
            for (int it = 0; it < 32; ++it)
                w3s[tid + it * 256] = ps_w3[tid + it * 256];
            __syncthreads();

            float a3[8][2];
            #pragma unroll
            for (int j = 0; j < 8; ++j) { a3[j][0] = 0.f; a3[j][1] = 0.f; }
            #pragma unroll 4
            for (int d2 = 0; d2 < H2DIM; ++d2) {
                float w0 = w3s[d2 * PNUM + cg];
                float w1v = w3s[d2 * PNUM + cg + 32];
                #pragma unroll
                for (int j = 0; j < 8; ++j) {
                    float x = h2[(rb0 + j) * 132 + d2];
                    a3[j][0] = fmaf(x, w0, a3[j][0]);
                    a3[j][1] = fmaf(x, w1v, a3[j][1]);
                }
            }
            int kind = g_mask_kind;
            #pragma unroll
            for (int j = 0; j < 8; ++j) {
                int row  = rb0 + j;
                int grow = base + row;
                if (grow >= NB) continue;
                size_t n = (size_t)nid[row];
                #pragma unroll
                for (int i = 0; i < 2; ++i) {
                    int p = cg + 32 * i;
                    float v = a3[j][i] + ps_b3[p];
                    size_t off = n * PNUM + p;
                    bool m;
                    if (kind == 0)      m = ((const unsigned char*)amask)[off] != 0;
                    else if (kind == 1) m = ((const int*)amask)[off] != 0;
                    else                m = ((const float*)amask)[off] != 0.f;
                    out_part[(size_t)grow * PNUM + p] = m ? v : -1e9f;
                }
            }
        }
    }
}

// ---------------------------------------------------------------------------
// Launcher
// ---------------------------------------------------------------------------
extern "C" void kernel_launch(void* const* d_in, const int* in_sizes, int n_in,
                              void* d_out, int out_size) {
    const float* node_emb   = (const float*)d_in[0];
    const float* region_emb = (const float*)d_in[1];
    const int*   boundary   = (const int*)d_in[2];
    const int*   nbidx      = (const int*)d_in[3];
    const int*   rbidx      = (const int*)d_in[4];
    const void*  amask      = d_in[5];
    const float* ge_w1 = (const float*)d_in[6];
    const float* ge_b1 = (const float*)d_in[7];
    const float* ge_w2 = (const float*)d_in[8];
    const float* ge_b2 = (const float*)d_in[9];
    const float* ns_w1 = (const float*)d_in[10];
    const float* ns_b1 = (const float*)d_in[11];
    const float* ns_w2 = (const float*)d_in[12];
    const float* ns_b2 = (const float*)d_in[13];
    const float* ns_w3 = (const float*)d_in[14];
    const float* ns_b3 = (const float*)d_in[15];
    const float* ps_w1 = (const float*)d_in[16];
    const float* ps_b1 = (const float*)d_in[17];
    const float* ps_w2 = (const float*)d_in[18];
    const float* ps_b2 = (const float*)d_in[19];
    const float* ps_w3 = (const float*)d_in[20];
    const float* ps_b3 = (const float*)d_in[21];

    const int NB = in_sizes[2];
    const int R  = in_sizes[4];
    const int maskElems = in_sizes[5];

    float* out_node = (float*)d_out;
    float* out_part = out_node + NB;

    // idempotent; legal during graph capture (not a stream operation)
    cudaFuncSetAttribute(k_main, cudaFuncAttributeMaxDynamicSharedMemorySize,
                         SMEM_BYTES);

    k_zero<<<(B_GRAPHS * D + 255) / 256, 256>>>();
    k_segsum<<<(R * D + 255) / 256, 256>>>(region_emb, rbidx, R);

    int nwords = maskElems / 4;          // safe lower bound on buffer words
    if (nwords > 65536) nwords = 65536;
    k_detect<<<1, 256>>>((const unsigned int*)amask, nwords);

    k_global<<<B_GRAPHS, 256>>>(ge_w1, ge_b1, ge_w2, ge_b2,
                                ns_w1, ns_b1, ps_w1, ps_b1);

    int grid = (NB + TM - 1) / TM;
    k_main<<<grid, 256, SMEM_BYTES>>>(node_emb, boundary, nbidx, amask,
                                      ns_w1, ns_w2, ns_b2, ns_w3, ns_b3,
                                      ps_w1, ps_w2, ps_b2, ps_w3, ps_b3,
                                      out_node, out_part, NB);
}